// round 12
// baseline (speedup 1.0000x reference)
#include <cuda_runtime.h>
#include <cuda_fp16.h>
#include <cstdint>

// ---------------------------------------------------------------------------
// out = concat( relu(A@relu(A@F)), A@(A@NF) ), N=8192, D=E=64.
// Both layers: C[8192,128] = A[8192,8192] @ W[8192,128], relu on cols<64.
// Path: single-digit fp16 HMMA + cp.async 4-stage pipeline, 512 threads
// (16 warps, warp tile 16x32) for latency hiding.
//   A pre-converted to fp16 (scaled by 2^13 -> [0,1), all normal).
//   C = (Ah@Bh) / 8192, fp32 accumulate.  Error ~2e-4 total (thresh 1e-3).
// ---------------------------------------------------------------------------

constexpr int NN  = 8192;
constexpr int WID = 128;

// smem stage: fp16 rows of 32 elems (64B) at pitch 80B (conflict-free ldmatrix)
constexpr int PITCH  = 80;
constexpr int AH_OFF = 0;                    // 64 rows  -> 5120 B
constexpr int BH_OFF = 5120;                 // 128 rows -> 10240 B
constexpr int BUF_BYTES = 15360;
constexpr int NSTAGE = 4;
constexpr int SMEM_GEMM = NSTAGE * BUF_BYTES;   // 61440 (>= 34816 epilogue)

__device__ __align__(16) __half g_Ah[(size_t)NN * NN];   // A * 2^13, fp16
__device__ __align__(16) __half g_B1[(size_t)WID * NN];  // [n][k]
__device__ __align__(16) __half g_B2[(size_t)WID * NN];

// ---------------------------------------------------------------------------
// helpers
// ---------------------------------------------------------------------------
__device__ __forceinline__ uint32_t s2u(const void* p) {
    uint32_t a;
    asm("{ .reg .u64 t; cvta.to.shared.u64 t, %1; cvt.u32.u64 %0, t; }"
        : "=r"(a) : "l"(p));
    return a;
}

__device__ __forceinline__ void ldmx4(uint32_t* r, uint32_t addr) {
    asm volatile("ldmatrix.sync.aligned.m8n8.x4.shared.b16 {%0,%1,%2,%3}, [%4];"
                 : "=r"(r[0]), "=r"(r[1]), "=r"(r[2]), "=r"(r[3]) : "r"(addr));
}

__device__ __forceinline__ void hmma(float* c, const uint32_t* a,
                                     const uint32_t* b) {
    asm volatile(
        "mma.sync.aligned.m16n8k16.row.col.f32.f16.f16.f32 "
        "{%0,%1,%2,%3}, {%4,%5,%6,%7}, {%8,%9}, {%0,%1,%2,%3};"
        : "+f"(c[0]), "+f"(c[1]), "+f"(c[2]), "+f"(c[3])
        : "r"(a[0]), "r"(a[1]), "r"(a[2]), "r"(a[3]), "r"(b[0]), "r"(b[1]));
}

__device__ __forceinline__ void cp16(uint32_t saddr, const void* gaddr) {
    asm volatile("cp.async.cg.shared.global [%0], [%1], 16;"
                 :: "r"(saddr), "l"(gaddr) : "memory");
}
#define CP_COMMIT() asm volatile("cp.async.commit_group;" ::: "memory")
#define CP_WAIT2()  asm volatile("cp.async.wait_group 2;" ::: "memory")

__device__ __forceinline__ uint32_t packh(__half a, __half b) {
    __half2 t = __halves2half2(a, b);
    return *reinterpret_cast<uint32_t*>(&t);
}

// ---------------------------------------------------------------------------
// conv_a: A fp32 -> fp16 * 2^13   (8 elems / thread)
// ---------------------------------------------------------------------------
__global__ __launch_bounds__(256) void conv_a(const float* __restrict__ A) {
    size_t i = (size_t)blockIdx.x * 256 + threadIdx.x;
    const float4* p = reinterpret_cast<const float4*>(A) + i * 2;
    float4 a = p[0], b = p[1];
    uint4 h = make_uint4(
        packh(__float2half_rn(a.x * 8192.0f), __float2half_rn(a.y * 8192.0f)),
        packh(__float2half_rn(a.z * 8192.0f), __float2half_rn(a.w * 8192.0f)),
        packh(__float2half_rn(b.x * 8192.0f), __float2half_rn(b.y * 8192.0f)),
        packh(__float2half_rn(b.z * 8192.0f), __float2half_rn(b.w * 8192.0f)));
    reinterpret_cast<uint4*>(g_Ah)[i] = h;
}

// ---------------------------------------------------------------------------
// conv_b1: transpose W=[F|NF] ([8192,64] each) -> g_B1 [n][k] fp16
// ---------------------------------------------------------------------------
__global__ void conv_b1(const float* __restrict__ F, const float* __restrict__ NF) {
    __shared__ float tile[32][33];
    int k0 = blockIdx.x * 32, n0 = blockIdx.y * 32;
    int tx = threadIdx.x, ty = threadIdx.y;              // (32, 8)
    const float* src = (n0 < 64) ? F : NF;
    int nc = (n0 < 64) ? n0 : (n0 - 64);
    #pragma unroll
    for (int j = 0; j < 4; ++j) {
        int r = ty + 8 * j;
        tile[r][tx] = src[(size_t)(k0 + r) * 64 + nc + tx];
    }
    __syncthreads();
    #pragma unroll
    for (int j = 0; j < 4; ++j) {
        int rn = ty + 8 * j;
        g_B1[(size_t)(n0 + rn) * NN + k0 + tx] = __float2half_rn(tile[tx][rn]);
    }
}

// ---------------------------------------------------------------------------
// one BK=32 chunk per warp: 6 ldmx4 + 8 HMMA (warp tile 16x32)
// ---------------------------------------------------------------------------
__device__ __forceinline__ void compute_tile(uint32_t base, uint32_t aLaneOff,
                                             uint32_t bLaneOff, int warp_m,
                                             int warp_n, float (&am)[4][4]) {
    const uint32_t aho = base + AH_OFF + warp_m * 1280 + aLaneOff;   // 16*80
    const uint32_t bho = base + BH_OFF + warp_n * 2560 + bLaneOff;   // 32*80
    #pragma unroll
    for (int ks = 0; ks < 2; ++ks) {
        uint32_t ah[4], bh[2][4];
        ldmx4(ah, aho + ks * 32);
        ldmx4(bh[0], bho + ks * 32);
        ldmx4(bh[1], bho + ks * 32 + 1280);
        #pragma unroll
        for (int nt = 0; nt < 4; ++nt)
            hmma(am[nt], ah, &bh[nt >> 1][(nt & 1) * 2]);
    }
}

// ---------------------------------------------------------------------------
// gemm_f16<LAYER>: C = A @ W via cp.async 4-stage pipeline, 512 threads.
// LAYER==1: epilogue -> g_B2 [n][k] fp16 (relu cols<64, transposed)
// LAYER==2: epilogue -> out fp32 [m][n]  (relu cols<64)
// ---------------------------------------------------------------------------
template <int LAYER>
__global__ __launch_bounds__(512, 1)
void gemm_f16(float* __restrict__ outp) {
    extern __shared__ char smem[];
    const uint32_t sb = s2u(smem);
    const int tid = threadIdx.x, lane = tid & 31, wid = tid >> 5;
    const int warp_m = wid >> 2, warp_n = wid & 3;      // 4 x 4 warps
    const int m0 = blockIdx.x * 64;

    const __half* __restrict__ B = (LAYER == 1) ? g_B1 : g_B2;

    // ldmatrix lane offsets
    const uint32_t aLaneOff = (lane & 15) * PITCH + (lane >> 4) * 16;
    const uint32_t n16 = (lane & 7) + ((lane >> 4) << 3);
    const uint32_t bLaneOff = n16 * PITCH + ((lane >> 3) & 1) * 16;

    // cp.async assignments: B 1 chunk per thread (512 chunks), A 1 chunk for
    // tid<256 (256 chunks). 16B each.
    const int  c16  = tid & 3;
    const int  brow = tid >> 2;                          // 0..127
    const __half* gB = B + (size_t)brow * NN + c16 * 8;
    const uint32_t sBoff = BH_OFF + brow * PITCH + c16 * 16;
    const bool doA = tid < 256;
    const int  arow = tid >> 2;                          // 0..63 when doA
    const __half* gA = g_Ah + (size_t)(m0 + arow) * NN + c16 * 8;
    const uint32_t sAoff = AH_OFF + arow * PITCH + c16 * 16;

    float am[4][4];
    #pragma unroll
    for (int j = 0; j < 4; ++j)
        #pragma unroll
        for (int q = 0; q < 4; ++q) am[j][q] = 0.0f;

    // ---- prologue: issue stages 0..2 ----
    #pragma unroll
    for (int s = 0; s < NSTAGE - 1; ++s) {
        const uint32_t bb = sb + (uint32_t)s * BUF_BYTES;
        const int kc = s * 32;
        if (doA) cp16(bb + sAoff, gA + kc);
        cp16(bb + sBoff, gB + kc);
        CP_COMMIT();
    }

    // ---- main loop: 256 chunks of BK=32 ----
    #pragma unroll 1
    for (int t = 0; t < 256; ++t) {
        CP_WAIT2();            // stage t landed (per-thread)
        __syncthreads();       // visible to all; all done reading buf (t-1)%4

        const int tp = t + NSTAGE - 1;
        if (tp < 256) {        // issue stage t+3
            const uint32_t bb = sb + (uint32_t)(tp & (NSTAGE - 1)) * BUF_BYTES;
            const int kc = tp * 32;
            if (doA) cp16(bb + sAoff, gA + kc);
            cp16(bb + sBoff, gB + kc);
        }
        CP_COMMIT();           // every iter (possibly empty group)

        compute_tile(sb + (uint32_t)(t & (NSTAGE - 1)) * BUF_BYTES,
                     aLaneOff, bLaneOff, warp_m, warp_n, am);
    }
    __syncthreads();

    // ---- epilogue: v = main / 8192, relu cols<64 ----
    const int r_base = warp_m * 16 + (lane >> 2);       // local row 0..63
    const int c_base = warp_n * 32 + (lane & 3) * 2;    // col 0..127
    constexpr float INV_SC = 1.0f / 8192.0f;

    if (LAYER == 1) {
        // stage fp32 [n][k] in smem (pitch 68 floats), then coalesced f16 out
        float* sE = reinterpret_cast<float*>(smem);
        #pragma unroll
        for (int nt = 0; nt < 4; ++nt) {
            int c = c_base + nt * 8;
            float v[4];
            #pragma unroll
            for (int q = 0; q < 4; ++q) v[q] = am[nt][q] * INV_SC;
            if (c < 64) {
                #pragma unroll
                for (int q = 0; q < 4; ++q) v[q] = fmaxf(v[q], 0.0f);
            }
            sE[(c    ) * 68 + r_base    ] = v[0];
            sE[(c + 1) * 68 + r_base    ] = v[1];
            sE[(c    ) * 68 + r_base + 8] = v[2];
            sE[(c + 1) * 68 + r_base + 8] = v[3];
        }
        __syncthreads();
        // 512 threads: n = tid>>2 (0..127), 16 k-values each
        const int n = tid >> 2, k0 = (tid & 3) * 16;
        const float* src = sE + n * 68 + k0;
        uint32_t w[8];
        #pragma unroll
        for (int j = 0; j < 8; ++j)
            w[j] = packh(__float2half_rn(src[2 * j]),
                         __float2half_rn(src[2 * j + 1]));
        uint4* dst = reinterpret_cast<uint4*>(g_B2 + (size_t)n * NN + m0 + k0);
        dst[0] = make_uint4(w[0], w[1], w[2], w[3]);
        dst[1] = make_uint4(w[4], w[5], w[6], w[7]);
    } else {
        #pragma unroll
        for (int nt = 0; nt < 4; ++nt) {
            int r = m0 + r_base;
            int c = c_base + nt * 8;
            float v[4];
            #pragma unroll
            for (int q = 0; q < 4; ++q) v[q] = am[nt][q] * INV_SC;
            if (c < 64) {
                #pragma unroll
                for (int q = 0; q < 4; ++q) v[q] = fmaxf(v[q], 0.0f);
            }
            *reinterpret_cast<float2*>(&outp[(size_t)r * WID + c]) =
                make_float2(v[0], v[1]);
            *reinterpret_cast<float2*>(&outp[(size_t)(r + 8) * WID + c]) =
                make_float2(v[2], v[3]);
        }
    }
}

// ---------------------------------------------------------------------------
// launch: conv_a + conv_b1 -> layer1 -> layer2. Graph-capturable,
// allocation-free, deterministic.
// ---------------------------------------------------------------------------
extern "C" void kernel_launch(void* const* d_in, const int* in_sizes, int n_in,
                              void* d_out, int out_size) {
    const float* A  = (const float*)d_in[0];
    const float* F  = (const float*)d_in[1];
    const float* NF = (const float*)d_in[2];
    float* out = (float*)d_out;

    cudaFuncSetAttribute(gemm_f16<1>, cudaFuncAttributeMaxDynamicSharedMemorySize, SMEM_GEMM);
    cudaFuncSetAttribute(gemm_f16<2>, cudaFuncAttributeMaxDynamicSharedMemorySize, SMEM_GEMM);

    conv_a<<<(int)((size_t)NN * NN / 8 / 256), 256>>>(A);
    conv_b1<<<dim3(NN / 32, WID / 32), dim3(32, 8)>>>(F, NF);
    gemm_f16<1><<<NN / 64, 512, SMEM_GEMM>>>(nullptr);
    gemm_f16<2><<<NN / 64, 512, SMEM_GEMM>>>(out);
}

// round 13
// speedup vs baseline: 1.1300x; 1.1300x over previous
#include <cuda_runtime.h>
#include <cuda_fp16.h>
#include <cstdint>

// ---------------------------------------------------------------------------
// out = concat( relu(A@relu(A@F)), A@(A@NF) ), N=8192, D=E=64.
// Both layers: C[8192,128] = A[8192,8192] @ W[8192,128], relu on cols<64.
// Path: single-digit fp16 HMMA, cp.async 4-stage pipeline, 256 threads,
// SPLIT-K=2 (grid 128x2, fp32 partials, deterministic fixed-order reduce).
//   A pre-converted to fp16 (scaled by 2^13 -> [0,1), all normal).
//   C = (Ah@Bh) / 8192, fp32 accumulate.  Error ~2e-4 total (thresh 1e-3).
// ---------------------------------------------------------------------------

constexpr int NN  = 8192;
constexpr int WID = 128;
constexpr int KSPLIT = 2;
constexpr int KHALF  = NN / KSPLIT;          // 4096 -> 128 iters of BK=32

// smem stage: fp16 rows of 32 elems (64B) at pitch 80B (conflict-free ldmatrix)
constexpr int PITCH  = 80;
constexpr int AH_OFF = 0;                    // 64 rows  -> 5120 B
constexpr int BH_OFF = 5120;                 // 128 rows -> 10240 B
constexpr int BUF_BYTES = 15360;
constexpr int NSTAGE = 4;
constexpr int SMEM_GEMM = NSTAGE * BUF_BYTES;   // 61440 -> 2 CTAs/SM

__device__ __align__(16) __half g_Ah[(size_t)NN * NN];      // A * 2^13, fp16
__device__ __align__(16) __half g_B1[(size_t)WID * NN];     // [n][k]
__device__ __align__(16) __half g_B2[(size_t)WID * NN];
__device__ __align__(16) float  g_part[(size_t)KSPLIT * NN * WID];  // partials

// ---------------------------------------------------------------------------
// helpers
// ---------------------------------------------------------------------------
__device__ __forceinline__ uint32_t s2u(const void* p) {
    uint32_t a;
    asm("{ .reg .u64 t; cvta.to.shared.u64 t, %1; cvt.u32.u64 %0, t; }"
        : "=r"(a) : "l"(p));
    return a;
}

__device__ __forceinline__ void ldmx4(uint32_t* r, uint32_t addr) {
    asm volatile("ldmatrix.sync.aligned.m8n8.x4.shared.b16 {%0,%1,%2,%3}, [%4];"
                 : "=r"(r[0]), "=r"(r[1]), "=r"(r[2]), "=r"(r[3]) : "r"(addr));
}

__device__ __forceinline__ void hmma(float* c, const uint32_t* a,
                                     const uint32_t* b) {
    asm volatile(
        "mma.sync.aligned.m16n8k16.row.col.f32.f16.f16.f32 "
        "{%0,%1,%2,%3}, {%4,%5,%6,%7}, {%8,%9}, {%0,%1,%2,%3};"
        : "+f"(c[0]), "+f"(c[1]), "+f"(c[2]), "+f"(c[3])
        : "r"(a[0]), "r"(a[1]), "r"(a[2]), "r"(a[3]), "r"(b[0]), "r"(b[1]));
}

__device__ __forceinline__ void cp16(uint32_t saddr, const void* gaddr) {
    asm volatile("cp.async.cg.shared.global [%0], [%1], 16;"
                 :: "r"(saddr), "l"(gaddr) : "memory");
}
#define CP_COMMIT() asm volatile("cp.async.commit_group;" ::: "memory")
#define CP_WAIT2()  asm volatile("cp.async.wait_group 2;" ::: "memory")

__device__ __forceinline__ uint32_t packh(__half a, __half b) {
    __half2 t = __halves2half2(a, b);
    return *reinterpret_cast<uint32_t*>(&t);
}

// ---------------------------------------------------------------------------
// conv_a: A fp32 -> fp16 * 2^13   (8 elems / thread)
// ---------------------------------------------------------------------------
__global__ __launch_bounds__(256) void conv_a(const float* __restrict__ A) {
    size_t i = (size_t)blockIdx.x * 256 + threadIdx.x;
    const float4* p = reinterpret_cast<const float4*>(A) + i * 2;
    float4 a = p[0], b = p[1];
    uint4 h = make_uint4(
        packh(__float2half_rn(a.x * 8192.0f), __float2half_rn(a.y * 8192.0f)),
        packh(__float2half_rn(a.z * 8192.0f), __float2half_rn(a.w * 8192.0f)),
        packh(__float2half_rn(b.x * 8192.0f), __float2half_rn(b.y * 8192.0f)),
        packh(__float2half_rn(b.z * 8192.0f), __float2half_rn(b.w * 8192.0f)));
    reinterpret_cast<uint4*>(g_Ah)[i] = h;
}

// ---------------------------------------------------------------------------
// conv_b1: transpose W=[F|NF] ([8192,64] each) -> g_B1 [n][k] fp16
// ---------------------------------------------------------------------------
__global__ void conv_b1(const float* __restrict__ F, const float* __restrict__ NF) {
    __shared__ float tile[32][33];
    int k0 = blockIdx.x * 32, n0 = blockIdx.y * 32;
    int tx = threadIdx.x, ty = threadIdx.y;              // (32, 8)
    const float* src = (n0 < 64) ? F : NF;
    int nc = (n0 < 64) ? n0 : (n0 - 64);
    #pragma unroll
    for (int j = 0; j < 4; ++j) {
        int r = ty + 8 * j;
        tile[r][tx] = src[(size_t)(k0 + r) * 64 + nc + tx];
    }
    __syncthreads();
    #pragma unroll
    for (int j = 0; j < 4; ++j) {
        int rn = ty + 8 * j;
        g_B1[(size_t)(n0 + rn) * NN + k0 + tx] = __float2half_rn(tile[tx][rn]);
    }
}

// ---------------------------------------------------------------------------
// one BK=32 chunk: 8 ldmx4 + 16 HMMA (warp tile 32x32, 8 warps = 2x4)
// ---------------------------------------------------------------------------
__device__ __forceinline__ void compute_tile(uint32_t base, uint32_t aLaneOff,
                                             uint32_t bLaneOff, int warp_m,
                                             int warp_n, float (&am)[2][4][4]) {
    const uint32_t aho = base + AH_OFF + warp_m * 2560 + aLaneOff;
    const uint32_t bho = base + BH_OFF + warp_n * 2560 + bLaneOff;
    #pragma unroll
    for (int ks = 0; ks < 2; ++ks) {
        uint32_t ah[2][4], bh[2][4];
        ldmx4(ah[0], aho + ks * 32);
        ldmx4(ah[1], aho + ks * 32 + 1280);
        ldmx4(bh[0], bho + ks * 32);
        ldmx4(bh[1], bho + ks * 32 + 1280);
        #pragma unroll
        for (int mt = 0; mt < 2; ++mt)
            #pragma unroll
            for (int nt = 0; nt < 4; ++nt)
                hmma(am[mt][nt], ah[mt], &bh[nt >> 1][(nt & 1) * 2]);
    }
}

// ---------------------------------------------------------------------------
// gemm_f16<LAYER>: partial[split] = A[:, kh] @ W[kh, :]  (fp32, no epilogue)
// grid (128 m-tiles, KSPLIT), 256 threads, 4-stage cp.async, 2 CTAs/SM.
// ---------------------------------------------------------------------------
template <int LAYER>
__global__ __launch_bounds__(256, 2)
void gemm_f16() {
    extern __shared__ char smem[];
    const uint32_t sb = s2u(smem);
    const int tid = threadIdx.x, lane = tid & 31, wid = tid >> 5;
    const int warp_m = wid >> 2, warp_n = wid & 3;
    const int m0 = blockIdx.x * 64;
    const int split = blockIdx.y;
    const int kb = split * KHALF;

    const __half* __restrict__ B = (LAYER == 1) ? g_B1 : g_B2;

    // ldmatrix lane offsets
    const uint32_t aLaneOff = (lane & 15) * PITCH + (lane >> 4) * 16;
    const uint32_t n16 = (lane & 7) + ((lane >> 4) << 3);
    const uint32_t bLaneOff = n16 * PITCH + ((lane >> 3) & 1) * 16;

    // cp.async assignments (16B chunks): A 1/thread, B 2/thread
    const int arow = tid >> 2, c16 = tid & 3;
    const __half* gA = g_Ah + (size_t)(m0 + arow) * NN + kb + c16 * 8;
    const uint32_t sAoff = AH_OFF + arow * PITCH + c16 * 16;
    const int brow0 = tid >> 2, brow1 = brow0 + 64;
    const __half* gB0 = B + (size_t)brow0 * NN + kb + c16 * 8;
    const __half* gB1 = B + (size_t)brow1 * NN + kb + c16 * 8;
    const uint32_t sBoff0 = BH_OFF + brow0 * PITCH + c16 * 16;
    const uint32_t sBoff1 = BH_OFF + brow1 * PITCH + c16 * 16;

    float am[2][4][4];
    #pragma unroll
    for (int i = 0; i < 2; ++i)
        #pragma unroll
        for (int j = 0; j < 4; ++j)
            #pragma unroll
            for (int q = 0; q < 4; ++q) am[i][j][q] = 0.0f;

    constexpr int NT = KHALF / 32;           // 128 iters

    // ---- prologue: issue stages 0..2 ----
    #pragma unroll
    for (int s = 0; s < NSTAGE - 1; ++s) {
        const uint32_t bb = sb + (uint32_t)s * BUF_BYTES;
        const int kc = s * 32;
        cp16(bb + sAoff,  gA  + kc);
        cp16(bb + sBoff0, gB0 + kc);
        cp16(bb + sBoff1, gB1 + kc);
        CP_COMMIT();
    }

    // ---- main loop ----
    #pragma unroll 1
    for (int t = 0; t < NT; ++t) {
        CP_WAIT2();
        __syncthreads();

        const int tp = t + NSTAGE - 1;
        if (tp < NT) {
            const uint32_t bb = sb + (uint32_t)(tp & (NSTAGE - 1)) * BUF_BYTES;
            const int kc = tp * 32;
            cp16(bb + sAoff,  gA  + kc);
            cp16(bb + sBoff0, gB0 + kc);
            cp16(bb + sBoff1, gB1 + kc);
        }
        CP_COMMIT();

        compute_tile(sb + (uint32_t)(t & (NSTAGE - 1)) * BUF_BYTES,
                     aLaneOff, bLaneOff, warp_m, warp_n, am);
    }

    // ---- store raw fp32 partial [m][n] (scale/relu applied in reduce) ----
    float* dst = g_part + (size_t)split * NN * WID;
    const int r_base = warp_m * 32 + (lane >> 2);
    const int c_base = warp_n * 32 + (lane & 3) * 2;
    #pragma unroll
    for (int mt = 0; mt < 2; ++mt)
        #pragma unroll
        for (int nt = 0; nt < 4; ++nt) {
            int r = m0 + r_base + mt * 16;
            int c = c_base + nt * 8;
            *reinterpret_cast<float2*>(&dst[(size_t)r * WID + c]) =
                make_float2(am[mt][nt][0], am[mt][nt][1]);
            *reinterpret_cast<float2*>(&dst[(size_t)(r + 8) * WID + c]) =
                make_float2(am[mt][nt][2], am[mt][nt][3]);
        }
}

// ---------------------------------------------------------------------------
// reduce_l1: g_B2[n][k] = f16( relu_{n<64}( (p0+p1)[k][n] / 8192 ) )
// transpose via 32x32 smem tile.  grid (256, 4), block (32, 8).
// ---------------------------------------------------------------------------
__global__ void reduce_l1() {
    __shared__ float tile[32][33];
    int k0 = blockIdx.x * 32, n0 = blockIdx.y * 32;
    int tx = threadIdx.x, ty = threadIdx.y;
    const float* p0 = g_part;
    const float* p1 = g_part + (size_t)NN * WID;
    const bool doRelu = (n0 + 31) < 64 || n0 < 64;   // per-elem check below
    #pragma unroll
    for (int j = 0; j < 4; ++j) {
        int r = ty + 8 * j;                           // m-local
        size_t o = (size_t)(k0 + r) * WID + n0 + tx;
        float v = (p0[o] + p1[o]) * (1.0f / 8192.0f);
        if (n0 + tx < 64) v = fmaxf(v, 0.0f);
        tile[r][tx] = v;
    }
    (void)doRelu;
    __syncthreads();
    #pragma unroll
    for (int j = 0; j < 4; ++j) {
        int rn = ty + 8 * j;                          // n-local
        g_B2[(size_t)(n0 + rn) * NN + k0 + tx] = __float2half_rn(tile[tx][rn]);
    }
}

// ---------------------------------------------------------------------------
// reduce_l2: out[m][n] = relu_{n<64}( (p0+p1)/8192 )   (float4 vectorized)
// ---------------------------------------------------------------------------
__global__ __launch_bounds__(256) void reduce_l2(float* __restrict__ outp) {
    size_t i4 = (size_t)blockIdx.x * 256 + threadIdx.x;   // over NN*WID/4
    const float4* p0 = reinterpret_cast<const float4*>(g_part);
    const float4* p1 = reinterpret_cast<const float4*>(g_part + (size_t)NN * WID);
    float4 a = p0[i4], b = p1[i4];
    float4 v = make_float4((a.x + b.x) * (1.0f / 8192.0f),
                           (a.y + b.y) * (1.0f / 8192.0f),
                           (a.z + b.z) * (1.0f / 8192.0f),
                           (a.w + b.w) * (1.0f / 8192.0f));
    if (((i4 * 4) & 127) < 64) {                     // cols<64 -> relu
        v.x = fmaxf(v.x, 0.0f); v.y = fmaxf(v.y, 0.0f);
        v.z = fmaxf(v.z, 0.0f); v.w = fmaxf(v.w, 0.0f);
    }
    reinterpret_cast<float4*>(outp)[i4] = v;
}

// ---------------------------------------------------------------------------
// launch chain. Graph-capturable, allocation-free, deterministic.
// ---------------------------------------------------------------------------
extern "C" void kernel_launch(void* const* d_in, const int* in_sizes, int n_in,
                              void* d_out, int out_size) {
    const float* A  = (const float*)d_in[0];
    const float* F  = (const float*)d_in[1];
    const float* NF = (const float*)d_in[2];
    float* out = (float*)d_out;

    cudaFuncSetAttribute(gemm_f16<1>, cudaFuncAttributeMaxDynamicSharedMemorySize, SMEM_GEMM);
    cudaFuncSetAttribute(gemm_f16<2>, cudaFuncAttributeMaxDynamicSharedMemorySize, SMEM_GEMM);

    conv_a<<<(int)((size_t)NN * NN / 8 / 256), 256>>>(A);
    conv_b1<<<dim3(NN / 32, WID / 32), dim3(32, 8)>>>(F, NF);
    gemm_f16<1><<<dim3(NN / 64, KSPLIT), 256, SMEM_GEMM>>>();
    reduce_l1<<<dim3(NN / 32, WID / 32), dim3(32, 8)>>>();
    gemm_f16<2><<<dim3(NN / 64, KSPLIT), 256, SMEM_GEMM>>>();
    reduce_l2<<<(NN * WID / 4) / 256, 256>>>(out);
}